// round 7
// baseline (speedup 1.0000x reference)
#include <cuda_runtime.h>
#include <cstdint>

#define B_      2048
#define D_      512
#define NA_     512
#define CAP_    32
#define NVMAX_  8
#define WARPS_  4
#define RPW_    128       // rows per warp (512 / 4 warps)
#define DEPTH_  2         // cp.async ring depth (rows in flight per warp)

// ---------------- device scratch ----------------
__device__ int g_counts[NA_];
__device__ int g_buckets[NA_ * CAP_];
__device__ int g_ovf_count;
__device__ int g_ovf[B_];

// ---------------- kernel 1: zero + bucket ----------------
__global__ void k_prep(const int* __restrict__ attrs) {
    int tid = threadIdx.x;                 // 1024 threads, 1 block
    if (tid < NA_) g_counts[tid] = 0;
    if (tid == NA_) g_ovf_count = 0;
    __syncthreads();
    for (int b = tid; b < B_; b += 1024) {
        int a = attrs[b];
        int pos = atomicAdd(&g_counts[a], 1);
        if (pos < CAP_) {
            g_buckets[a * CAP_ + pos] = b;
        } else {
            int o = atomicAdd(&g_ovf_count, 1);
            g_ovf[o] = b;
        }
    }
}

// ---------------- cp.async helpers ----------------
__device__ __forceinline__ void cp16(uint32_t saddr, const void* gaddr) {
    asm volatile("cp.async.cg.shared.global [%0], [%1], 16;"
                 :: "r"(saddr), "l"(gaddr));
}
__device__ __forceinline__ void cp_commit() {
    asm volatile("cp.async.commit_group;");
}
template <int N>
__device__ __forceinline__ void cp_wait() {
    asm volatile("cp.async.wait_group %0;" :: "n"(N));
}

// lane copies its own 4x16B chunks of one 2KB matrix row (same-lane readback,
// so only wait_group is needed — no syncwarp in the row loop)
__device__ __forceinline__ void issue_row(uint32_t sbase, const float4* grow, int lane) {
    cp16(sbase + (uint32_t)(lane)      * 16, grow + lane);
    cp16(sbase + (uint32_t)(32 + lane) * 16, grow + 32 + lane);
    cp16(sbase + (uint32_t)(64 + lane) * 16, grow + 64 + lane);
    cp16(sbase + (uint32_t)(96 + lane) * 16, grow + 96 + lane);
    cp_commit();
}

// ---------------- per-row compute: 4 reg-samples (+4 smem-samples) -------
template <int NV>
__device__ __forceinline__ void do_row(
    const float4* __restrict__ ringrow,   // smem, this warp's slot
    const float4 v[4][4],                 // register-resident vectors j=0..3
    const float4* __restrict__ sv4,       // smem vectors j=4..7 ([4][128])
    const int*    __restrict__ ssamp,
    int nv, float* __restrict__ out, int row, int lane)
{
    float4 m0 = ringrow[lane];
    float4 m1 = ringrow[32 + lane];
    float4 m2 = ringrow[64 + lane];
    float4 m3 = ringrow[96 + lane];

    float acc[NV];
#pragma unroll
    for (int j = 0; j < 4; j++) {
        float x;
        x = m0.x * v[j][0].x;
        x = fmaf(m0.y, v[j][0].y, x);
        x = fmaf(m0.z, v[j][0].z, x);
        x = fmaf(m0.w, v[j][0].w, x);
        x = fmaf(m1.x, v[j][1].x, x);
        x = fmaf(m1.y, v[j][1].y, x);
        x = fmaf(m1.z, v[j][1].z, x);
        x = fmaf(m1.w, v[j][1].w, x);
        x = fmaf(m2.x, v[j][2].x, x);
        x = fmaf(m2.y, v[j][2].y, x);
        x = fmaf(m2.z, v[j][2].z, x);
        x = fmaf(m2.w, v[j][2].w, x);
        x = fmaf(m3.x, v[j][3].x, x);
        x = fmaf(m3.y, v[j][3].y, x);
        x = fmaf(m3.z, v[j][3].z, x);
        x = fmaf(m3.w, v[j][3].w, x);
        acc[j] = x;
    }
    if (NV == 8) {
#pragma unroll
        for (int j = 0; j < 4; j++) {
            float4 w0 = sv4[j * 128 + lane];
            float4 w1 = sv4[j * 128 + 32 + lane];
            float4 w2 = sv4[j * 128 + 64 + lane];
            float4 w3 = sv4[j * 128 + 96 + lane];
            float x;
            x = m0.x * w0.x;
            x = fmaf(m0.y, w0.y, x);
            x = fmaf(m0.z, w0.z, x);
            x = fmaf(m0.w, w0.w, x);
            x = fmaf(m1.x, w1.x, x);
            x = fmaf(m1.y, w1.y, x);
            x = fmaf(m1.z, w1.z, x);
            x = fmaf(m1.w, w1.w, x);
            x = fmaf(m2.x, w2.x, x);
            x = fmaf(m2.y, w2.y, x);
            x = fmaf(m2.z, w2.z, x);
            x = fmaf(m2.w, w2.w, x);
            x = fmaf(m3.x, w3.x, x);
            x = fmaf(m3.y, w3.y, x);
            x = fmaf(m3.z, w3.z, x);
            x = fmaf(m3.w, w3.w, x);
            acc[4 + j] = x;
        }
    }

#pragma unroll
    for (int j = 0; j < NV; j++) {
        float x = acc[j];
        x += __shfl_xor_sync(0xffffffffu, x, 16);
        x += __shfl_xor_sync(0xffffffffu, x, 8);
        x += __shfl_xor_sync(0xffffffffu, x, 4);
        x += __shfl_xor_sync(0xffffffffu, x, 2);
        x += __shfl_xor_sync(0xffffffffu, x, 1);
        if (lane == j && j < nv)
            out[(size_t)ssamp[j] * D_ + row] = (x > 0.0f) ? x : 0.0f;
    }
}

// ---------------- per-warp pass over 128 rows with cp.async ring ---------
template <int NV>
__device__ __forceinline__ void run_pass(
    const float* __restrict__ M,
    float4* __restrict__ ring,            // [DEPTH_][128] this warp's ring
    uint32_t ring_s,                      // shared address of same
    const float4 v[4][4],
    const float4* __restrict__ sv4,
    const int* __restrict__ ssamp,
    int nv, float* __restrict__ out, int warp, int lane)
{
    const float4* g = (const float4*)M + (size_t)warp * RPW_ * 128;

    issue_row(ring_s,        g,       lane);   // row 0 -> slot 0
    issue_row(ring_s + 2048, g + 128, lane);   // row 1 -> slot 1

#pragma unroll 1
    for (int r = 0; r < RPW_ - 1; r++) {
        cp_wait<DEPTH_ - 1>();
        int slot = r & 1;
        // refill slot with row r+2 AFTER reads below are issued? reads are
        // LDS inside do_row; cp.async write lands >=L2 latency later — safe.
        do_row<NV>(ring + slot * 128, v, sv4, ssamp, nv, out,
                   warp * RPW_ + r, lane);
        if (r + DEPTH_ < RPW_)
            issue_row(ring_s + (uint32_t)slot * 2048, g + (r + DEPTH_) * 128, lane);
    }
    cp_wait<0>();
    do_row<NV>(ring + ((RPW_ - 1) & 1) * 128, v, sv4, ssamp, nv, out,
               warp * RPW_ + RPW_ - 1, lane);
}

// ---------------- kernel 2: per-attribute matvec ------------------------
// grid = NA_, 128 threads (4 warps). Warp owns 128 contiguous rows.
__global__ __launch_bounds__(128) void k_compute(
    const int*   __restrict__ attrs,
    const int*   __restrict__ objs,
    const float* __restrict__ attr_ops,
    const float* __restrict__ obj_emb,
    float*       __restrict__ out)
{
    __shared__ float4 ring[WARPS_][DEPTH_][128];   // 16 KB
    __shared__ float4 sv[4 * 128];                 // 8 KB (samples 4..7)
    __shared__ int    ssamp[NVMAX_];

    int tid  = threadIdx.x;
    int lane = tid & 31;
    int warp = tid >> 5;
    int a    = blockIdx.x;

    int cnt = g_counts[a];
    if (cnt > CAP_) cnt = CAP_;
    const float* M = attr_ops + (size_t)a * D_ * D_;
    uint32_t ring_s = (uint32_t)__cvta_generic_to_shared(&ring[warp][0][0]);

    for (int base = 0; base < cnt; base += NVMAX_) {
        int nv = cnt - base;
        if (nv > NVMAX_) nv = NVMAX_;

        __syncthreads();
        if (tid < nv) ssamp[tid] = g_buckets[a * CAP_ + base + tid];
        __syncthreads();

        // register-resident vectors j = 0..3 (zero-padded)
        float4 v[4][4];
#pragma unroll
        for (int j = 0; j < 4; j++) {
            if (j < nv) {
                const float4* p = (const float4*)(obj_emb + (size_t)objs[ssamp[j]] * D_);
                v[j][0] = p[lane];
                v[j][1] = p[32 + lane];
                v[j][2] = p[64 + lane];
                v[j][3] = p[96 + lane];
            } else {
                v[j][0] = v[j][1] = v[j][2] = v[j][3] = make_float4(0.f, 0.f, 0.f, 0.f);
            }
        }

        if (nv > 4) {
            // smem vectors j = 4..7 (zero-padded)
            for (int u = tid; u < 4 * 128; u += 128) {
                int jj = 4 + (u >> 7);
                float4 val = make_float4(0.f, 0.f, 0.f, 0.f);
                if (jj < nv)
                    val = ((const float4*)(obj_emb + (size_t)objs[ssamp[jj]] * D_))[u & 127];
                sv[u] = val;
            }
            __syncthreads();
            run_pass<8>(M, &ring[warp][0][0], ring_s, v, sv, ssamp, nv, out, warp, lane);
        } else {
            run_pass<4>(M, &ring[warp][0][0], ring_s, v, sv, ssamp, nv, out, warp, lane);
        }
    }

    // ---- overflow tail (rare; correctness safety net) ----
    int novf = g_ovf_count;
    for (int i = blockIdx.x; i < novf; i += gridDim.x) {
        __syncthreads();
        if (tid == 0) ssamp[0] = g_ovf[i];
        __syncthreads();
        int b = ssamp[0];
        const float4* p = (const float4*)(obj_emb + (size_t)objs[b] * D_);
        float4 v[4][4];
        v[0][0] = p[lane]; v[0][1] = p[32 + lane];
        v[0][2] = p[64 + lane]; v[0][3] = p[96 + lane];
#pragma unroll
        for (int j = 1; j < 4; j++)
            v[j][0] = v[j][1] = v[j][2] = v[j][3] = make_float4(0.f, 0.f, 0.f, 0.f);
        run_pass<4>(attr_ops + (size_t)attrs[b] * D_ * D_,
                    &ring[warp][0][0], ring_s, v, sv, ssamp, 1, out, warp, lane);
    }
}

// ---------------- launch -------------------------------------------------
extern "C" void kernel_launch(void* const* d_in, const int* in_sizes, int n_in,
                              void* d_out, int out_size)
{
    const int*   attrs    = (const int*)d_in[0];
    const int*   objs     = (const int*)d_in[1];
    const float* attr_ops = (const float*)d_in[2];
    const float* obj_emb  = (const float*)d_in[3];
    float*       out      = (float*)d_out;

    k_prep<<<1, 1024>>>(attrs);
    k_compute<<<NA_, 128>>>(attrs, objs, attr_ops, obj_emb, out);
}

// round 8
// speedup vs baseline: 1.8081x; 1.8081x over previous
#include <cuda_runtime.h>
#include <cstdint>

#define B_      2048
#define D_      512
#define NA_     512
#define CAP_    32
#define NVMAX_  8
#define WARPS_  8
#define NSL_    2
#define RPW_    32        // rows per warp: 512 / (8 warps * 2 slices)
#define DEPTH_  3         // cp.async ring depth (rows in flight per warp)
#define RING4_  (DEPTH_ * 128)            // float4 per warp ring
#define SV4OFF_ (WARPS_ * RING4_)         // 3072
#define SMEMB_  ((WARPS_ * RING4_ + NVMAX_ * 128 + 8) * 16)   // 65664 B

// ---------------- device scratch ----------------
__device__ int g_counts[NA_];
__device__ int g_buckets[NA_ * CAP_];
__device__ int g_ovf_count;
__device__ int g_ovf[B_];

// ---------------- kernel 1: zero + bucket ----------------
__global__ void k_prep(const int* __restrict__ attrs) {
    int tid = threadIdx.x;                 // 1024 threads, 1 block
    if (tid < NA_) g_counts[tid] = 0;
    if (tid == NA_) g_ovf_count = 0;
    __syncthreads();
    for (int b = tid; b < B_; b += 1024) {
        int a = attrs[b];
        int pos = atomicAdd(&g_counts[a], 1);
        if (pos < CAP_) {
            g_buckets[a * CAP_ + pos] = b;
        } else {
            int o = atomicAdd(&g_ovf_count, 1);
            g_ovf[o] = b;
        }
    }
}

// ---------------- cp.async helpers ----------------
__device__ __forceinline__ void cp16(uint32_t saddr, const void* gaddr) {
    asm volatile("cp.async.cg.shared.global [%0], [%1], 16;"
                 :: "r"(saddr), "l"(gaddr));
}
__device__ __forceinline__ void cp_commit() {
    asm volatile("cp.async.commit_group;");
}
template <int N>
__device__ __forceinline__ void cp_wait() {
    asm volatile("cp.async.wait_group %0;" :: "n"(N));
}

// lane copies its own 4x16B chunks of one 2KB matrix row; readback is
// same-lane, so wait_group alone orders it (validated R7, rel_err 1.8e-7)
__device__ __forceinline__ void issue_row(uint32_t sbase, const float4* grow, int lane) {
    cp16(sbase + (uint32_t)(lane)      * 16, grow + lane);
    cp16(sbase + (uint32_t)(32 + lane) * 16, grow + 32 + lane);
    cp16(sbase + (uint32_t)(64 + lane) * 16, grow + 64 + lane);
    cp16(sbase + (uint32_t)(96 + lane) * 16, grow + 96 + lane);
    cp_commit();
}

// ---------------- j-loop: NV dot products for one row --------------------
template <int NV>
__device__ __forceinline__ void jloop(
    float4 m0, float4 m1, float4 m2, float4 m3,
    const float4* __restrict__ sv4, int nv,
    float* __restrict__ out, int row, int lane, int myS)
{
#pragma unroll
    for (int j = 0; j < NV; j++) {
        float4 v0 = sv4[j * 128 + lane];
        float4 v1 = sv4[j * 128 + 32 + lane];
        float4 v2 = sv4[j * 128 + 64 + lane];
        float4 v3 = sv4[j * 128 + 96 + lane];
        float x;
        x = m0.x * v0.x;
        x = fmaf(m0.y, v0.y, x);
        x = fmaf(m0.z, v0.z, x);
        x = fmaf(m0.w, v0.w, x);
        x = fmaf(m1.x, v1.x, x);
        x = fmaf(m1.y, v1.y, x);
        x = fmaf(m1.z, v1.z, x);
        x = fmaf(m1.w, v1.w, x);
        x = fmaf(m2.x, v2.x, x);
        x = fmaf(m2.y, v2.y, x);
        x = fmaf(m2.z, v2.z, x);
        x = fmaf(m2.w, v2.w, x);
        x = fmaf(m3.x, v3.x, x);
        x = fmaf(m3.y, v3.y, x);
        x = fmaf(m3.z, v3.z, x);
        x = fmaf(m3.w, v3.w, x);
        x += __shfl_xor_sync(0xffffffffu, x, 16);
        x += __shfl_xor_sync(0xffffffffu, x, 8);
        x += __shfl_xor_sync(0xffffffffu, x, 4);
        x += __shfl_xor_sync(0xffffffffu, x, 2);
        x += __shfl_xor_sync(0xffffffffu, x, 1);
        if (j < nv && lane == j)
            out[(size_t)myS * D_ + row] = (x > 0.0f) ? x : 0.0f;
    }
}

// ---------------- per-warp pass: 32 rows, cp.async ring depth 3 ----------
template <int NV>
__device__ __forceinline__ void run_pass(
    const float4* __restrict__ g,      // warp's 32-row matrix block (global)
    float4* __restrict__ ringw,        // [DEPTH_][128] this warp's ring
    uint32_t ring_s,
    const float4* __restrict__ sv4,
    int nv, float* __restrict__ out, int grow0, int lane, int myS)
{
    issue_row(ring_s,        g,       lane);
    issue_row(ring_s + 2048, g + 128, lane);
    issue_row(ring_s + 4096, g + 256, lane);

#pragma unroll 1
    for (int r = 0; r < RPW_ - 3; r++) {
        cp_wait<2>();
        const float4* sp = ringw + (r % 3) * 128;
        float4 m0 = sp[lane];
        float4 m1 = sp[32 + lane];
        float4 m2 = sp[64 + lane];
        float4 m3 = sp[96 + lane];
        issue_row(ring_s + (uint32_t)(r % 3) * 2048, g + (r + 3) * 128, lane);
        jloop<NV>(m0, m1, m2, m3, sv4, nv, out, grow0 + r, lane, myS);
    }
    {   // r = 29  (slot 29%3 = 2)
        cp_wait<2>();
        const float4* sp = ringw + 2 * 128;
        jloop<NV>(sp[lane], sp[32 + lane], sp[64 + lane], sp[96 + lane],
                  sv4, nv, out, grow0 + 29, lane, myS);
    }
    {   // r = 30  (slot 0)
        cp_wait<1>();
        const float4* sp = ringw;
        jloop<NV>(sp[lane], sp[32 + lane], sp[64 + lane], sp[96 + lane],
                  sv4, nv, out, grow0 + 30, lane, myS);
    }
    {   // r = 31  (slot 1)
        cp_wait<0>();
        const float4* sp = ringw + 128;
        jloop<NV>(sp[lane], sp[32 + lane], sp[64 + lane], sp[96 + lane],
                  sv4, nv, out, grow0 + 31, lane, myS);
    }
}

// ---------------- kernel 2: per-attribute matvec ------------------------
// grid = (NA_, NSL_), 256 threads (8 warps). Warp owns 32 contiguous rows.
__global__ __launch_bounds__(256) void k_compute(
    const int*   __restrict__ attrs,
    const int*   __restrict__ objs,
    const float* __restrict__ attr_ops,
    const float* __restrict__ obj_emb,
    float*       __restrict__ out)
{
    extern __shared__ float4 smem4[];
    float4* ring  = smem4;                       // [8][3][128]  48 KB
    float4* sv4   = smem4 + SV4OFF_;             // [8][128]     16 KB
    int*    ssamp = (int*)(smem4 + SV4OFF_ + NVMAX_ * 128);

    int tid  = threadIdx.x;
    int lane = tid & 31;
    int warp = tid >> 5;
    int a    = blockIdx.x;

    int cnt = g_counts[a];
    if (cnt > CAP_) cnt = CAP_;

    int grow0 = blockIdx.y * (WARPS_ * RPW_) + warp * RPW_;
    const float4* Mw =
        (const float4*)(attr_ops + (size_t)a * D_ * D_) + (size_t)grow0 * 128;
    float4*  ringw  = ring + warp * RING4_;
    uint32_t ring_s = (uint32_t)__cvta_generic_to_shared(ringw);

    for (int base = 0; base < cnt; base += NVMAX_) {
        int nv = cnt - base;
        if (nv > NVMAX_) nv = NVMAX_;
        int NVsel = (nv <= 1) ? 1 : (nv <= 2) ? 2 : (nv <= 4) ? 4 : 8;

        __syncthreads();                   // prior pass done reading sv
        if (tid < nv) ssamp[tid] = g_buckets[a * CAP_ + base + tid];
        __syncthreads();

        // load vectors, zero-padded to NVsel
        for (int u = tid; u < NVsel * 128; u += 256) {
            int j = u >> 7;
            float4 val = make_float4(0.f, 0.f, 0.f, 0.f);
            if (j < nv)
                val = ((const float4*)(obj_emb + (size_t)objs[ssamp[j]] * D_))[u & 127];
            sv4[u] = val;
        }
        __syncthreads();

        int myS = (lane < nv) ? ssamp[lane] : 0;

        switch (NVsel) {
            case 1: run_pass<1>(Mw, ringw, ring_s, sv4, nv, out, grow0, lane, myS); break;
            case 2: run_pass<2>(Mw, ringw, ring_s, sv4, nv, out, grow0, lane, myS); break;
            case 4: run_pass<4>(Mw, ringw, ring_s, sv4, nv, out, grow0, lane, myS); break;
            default: run_pass<8>(Mw, ringw, ring_s, sv4, nv, out, grow0, lane, myS); break;
        }
    }

    // ---- overflow tail (rare; correctness safety net) ----
    int novf = g_ovf_count;
    for (int i = blockIdx.x; i < novf; i += NA_) {
        __syncthreads();
        if (tid == 0) ssamp[0] = g_ovf[i];
        __syncthreads();
        int b = ssamp[0];
        for (int u = tid; u < 128; u += 256)
            sv4[u] = ((const float4*)(obj_emb + (size_t)objs[b] * D_))[u];
        __syncthreads();
        const float4* M2 =
            (const float4*)(attr_ops + (size_t)attrs[b] * D_ * D_) + (size_t)grow0 * 128;
        run_pass<1>(M2, ringw, ring_s, sv4, 1, out, grow0, lane, b);
    }
}

// ---------------- launch -------------------------------------------------
extern "C" void kernel_launch(void* const* d_in, const int* in_sizes, int n_in,
                              void* d_out, int out_size)
{
    const int*   attrs    = (const int*)d_in[0];
    const int*   objs     = (const int*)d_in[1];
    const float* attr_ops = (const float*)d_in[2];
    const float* obj_emb  = (const float*)d_in[3];
    float*       out      = (float*)d_out;

    cudaFuncSetAttribute(k_compute,
                         cudaFuncAttributeMaxDynamicSharedMemorySize, SMEMB_);

    k_prep<<<1, 1024>>>(attrs);
    k_compute<<<dim3(NA_, NSL_), 256, SMEMB_>>>(attrs, objs, attr_ops, obj_emb, out);
}

// round 9
// speedup vs baseline: 2.8445x; 1.5732x over previous
#include <cuda_runtime.h>
#include <cstdint>

#define B_      2048
#define D_      512
#define NA_     512
#define CAP_    32
#define NVMAX_  8
#define WARPS_  8
#define NSL_    2
#define RPW_    32                  // rows per warp: 512 / (8 warps * 2 slices)
#define KC_     32                  // k per chunk
#define NCH_    16                  // chunks per pass (512/32)
#define PITCH4_ 9                   // float4 per tile row (8 data + 1 pad)
#define SLOT4_  (RPW_ * PITCH4_)    // 288 float4 per slot
#define RING4_  (2 * SLOT4_)        // 576 float4 per warp (2 slots)
#define SV4OFF_ (WARPS_ * RING4_)   // 4608
#define SMEMB_  ((SV4OFF_ + NVMAX_ * 128) * 16 + 64)   // ~90.2 KB

// ---------------- device scratch ----------------
__device__ int g_counts[NA_];
__device__ int g_buckets[NA_ * CAP_];
__device__ int g_ovf_count;
__device__ int g_ovf[B_];

// ---------------- kernel 1: zero + bucket ----------------
__global__ void k_prep(const int* __restrict__ attrs) {
    int tid = threadIdx.x;                 // 1024 threads, 1 block
    if (tid < NA_) g_counts[tid] = 0;
    if (tid == NA_) g_ovf_count = 0;
    __syncthreads();
    for (int b = tid; b < B_; b += 1024) {
        int a = attrs[b];
        int pos = atomicAdd(&g_counts[a], 1);
        if (pos < CAP_) {
            g_buckets[a * CAP_ + pos] = b;
        } else {
            int o = atomicAdd(&g_ovf_count, 1);
            g_ovf[o] = b;
        }
    }
}

// ---------------- cp.async helpers ----------------
__device__ __forceinline__ void cp16(uint32_t saddr, const void* gaddr) {
    asm volatile("cp.async.cg.shared.global [%0], [%1], 16;"
                 :: "r"(saddr), "l"(gaddr));
}
__device__ __forceinline__ void cp_commit() {
    asm volatile("cp.async.commit_group;");
}
template <int N>
__device__ __forceinline__ void cp_wait() {
    asm volatile("cp.async.wait_group %0;" :: "n"(N));
}

// stage one k-chunk (32 rows x 32 k = 4KB) into a pitched smem slot.
// warp-instr i copies rows i*4..i*4+3 (4 full 128B lines, fully consumed);
// STS lands as 4 clean 128B wavefronts (rows at pitch 144B, 8-lane phases
// each cover one contiguous 128B span).
__device__ __forceinline__ void issue_chunk(
    uint32_t sslot, const float4* __restrict__ gbase, int c, int lane)
{
    int sub = lane >> 3;        // 0..3: row-within-group
    int off = lane & 7;         // 0..7: float4-within-row
    const float4* g = gbase + c * 8 + off;
#pragma unroll
    for (int i = 0; i < 8; i++) {
        int row = i * 4 + sub;
        cp16(sslot + (uint32_t)(row * PITCH4_ + off) * 16, g + (size_t)row * 128);
    }
    cp_commit();
}

// ---------------- per-warp pass: thread = row, vectors broadcast ---------
// Per k-quad: 1 matrix LDS.128 (pitch-9 conflict-free) + NV broadcast
// LDS.128 + 4*NV FFMA. acc fully reduced per-thread; coalesced store.
template <int NV>
__device__ __forceinline__ void run_pass(
    const float4* __restrict__ gbase,     // matrix + grow0*128 (float4)
    float4* __restrict__ slot0, float4* __restrict__ slot1,
    uint32_t s0, uint32_t s1,
    const float4* __restrict__ sv4,       // smem vectors [NV][128]
    const int* __restrict__ ssamp,
    int nv, float* __restrict__ out, int grow0, int lane)
{
    float acc[NV];
#pragma unroll
    for (int j = 0; j < NV; j++) acc[j] = 0.0f;

    issue_chunk(s0, gbase, 0, lane);
    issue_chunk(s1, gbase, 1, lane);

#pragma unroll 1
    for (int c = 0; c < NCH_; c++) {
        if (c < NCH_ - 1) cp_wait<1>(); else cp_wait<0>();
        __syncwarp();                     // cross-lane visibility of staged tile
        const float4* sp = (c & 1) ? slot1 : slot0;
#pragma unroll
        for (int k4 = 0; k4 < 8; k4++) {
            float4 m = sp[lane * PITCH4_ + k4];
#pragma unroll
            for (int j = 0; j < NV; j++) {
                float4 v = sv4[j * 128 + c * 8 + k4];   // broadcast
                acc[j] = fmaf(m.x, v.x, acc[j]);
                acc[j] = fmaf(m.y, v.y, acc[j]);
                acc[j] = fmaf(m.z, v.z, acc[j]);
                acc[j] = fmaf(m.w, v.w, acc[j]);
            }
        }
        if (c + 2 < NCH_) {
            __syncwarp();                 // all lanes done reading this slot
            issue_chunk((c & 1) ? s1 : s0, gbase, c + 2, lane);
        }
    }

    int row = grow0 + lane;
#pragma unroll
    for (int j = 0; j < NV; j++)
        if (j < nv)
            out[(size_t)ssamp[j] * D_ + row] = fmaxf(acc[j], 0.0f);
}

// ---------------- kernel 2: per-attribute matvec ------------------------
// grid = (NA_, NSL_), 256 threads (8 warps). Warp owns 32 contiguous rows.
__global__ __launch_bounds__(256) void k_compute(
    const int*   __restrict__ attrs,
    const int*   __restrict__ objs,
    const float* __restrict__ attr_ops,
    const float* __restrict__ obj_emb,
    float*       __restrict__ out)
{
    extern __shared__ float4 smem4[];
    float4* ring = smem4;                          // [8][2][288] f4
    float4* sv4  = smem4 + SV4OFF_;                // [8][128]   f4
    __shared__ int ssamp[NVMAX_];

    int tid  = threadIdx.x;
    int lane = tid & 31;
    int warp = tid >> 5;
    int a    = blockIdx.x;

    int cnt = g_counts[a];
    if (cnt > CAP_) cnt = CAP_;

    int grow0 = blockIdx.y * (WARPS_ * RPW_) + warp * RPW_;
    const float4* Mw =
        (const float4*)(attr_ops + (size_t)a * D_ * D_) + (size_t)grow0 * 128;

    float4*  slot0 = ring + warp * RING4_;
    float4*  slot1 = slot0 + SLOT4_;
    uint32_t s0 = (uint32_t)__cvta_generic_to_shared(slot0);
    uint32_t s1 = (uint32_t)__cvta_generic_to_shared(slot1);

    for (int base = 0; base < cnt; base += NVMAX_) {
        int nv = cnt - base;
        if (nv > NVMAX_) nv = NVMAX_;
        int NVsel = (nv <= 1) ? 1 : (nv <= 2) ? 2 : (nv <= 4) ? 4 : 8;

        __syncthreads();                   // prior pass done reading sv4
        if (tid < nv) ssamp[tid] = g_buckets[a * CAP_ + base + tid];
        __syncthreads();

        for (int u = tid; u < NVsel * 128; u += 256) {
            int j = u >> 7;
            float4 val = make_float4(0.f, 0.f, 0.f, 0.f);
            if (j < nv)
                val = ((const float4*)(obj_emb + (size_t)objs[ssamp[j]] * D_))[u & 127];
            sv4[u] = val;
        }
        __syncthreads();

        switch (NVsel) {
            case 1: run_pass<1>(Mw, slot0, slot1, s0, s1, sv4, ssamp, nv, out, grow0, lane); break;
            case 2: run_pass<2>(Mw, slot0, slot1, s0, s1, sv4, ssamp, nv, out, grow0, lane); break;
            case 4: run_pass<4>(Mw, slot0, slot1, s0, s1, sv4, ssamp, nv, out, grow0, lane); break;
            default: run_pass<8>(Mw, slot0, slot1, s0, s1, sv4, ssamp, nv, out, grow0, lane); break;
        }
    }

    // ---- overflow tail (rare; correctness safety net) ----
    int novf = g_ovf_count;
    for (int i = blockIdx.x; i < novf; i += NA_) {
        __syncthreads();
        if (tid == 0) ssamp[0] = g_ovf[i];
        __syncthreads();
        int b = ssamp[0];
        for (int u = tid; u < 128; u += 256)
            sv4[u] = ((const float4*)(obj_emb + (size_t)objs[b] * D_))[u];
        __syncthreads();
        if (tid == 0) ssamp[0] = b;
        __syncthreads();
        const float4* M2 =
            (const float4*)(attr_ops + (size_t)attrs[b] * D_ * D_) + (size_t)grow0 * 128;
        run_pass<1>(M2, slot0, slot1, s0, s1, sv4, ssamp, 1, out, grow0, lane);
    }
}

// ---------------- launch -------------------------------------------------
extern "C" void kernel_launch(void* const* d_in, const int* in_sizes, int n_in,
                              void* d_out, int out_size)
{
    const int*   attrs    = (const int*)d_in[0];
    const int*   objs     = (const int*)d_in[1];
    const float* attr_ops = (const float*)d_in[2];
    const float* obj_emb  = (const float*)d_in[3];
    float*       out      = (float*)d_out;

    cudaFuncSetAttribute(k_compute,
                         cudaFuncAttributeMaxDynamicSharedMemorySize, SMEMB_);

    k_prep<<<1, 1024>>>(attrs);
    k_compute<<<dim3(NA_, NSL_), 256, SMEMB_>>>(attrs, objs, attr_ops, obj_emb, out);
}